// round 14
// baseline (speedup 1.0000x reference)
#include <cuda_runtime.h>
#include <cuda_fp16.h>
#include <cstdint>

// ---------------------------------------------------------------------------
// Fastformer — fp16 SS mma.sync GEMMs (4-stage, 2 CTA/SM, round-12 core),
// kg-scale fused into gemm_out A-fragments, fp16 Q emitted by gemm_qk.
// ---------------------------------------------------------------------------

#define Bc 8
#define Sc 2048
#define Dc 1024
#define Hc 16
#define DHc 64
#define Mc (Bc * Sc)   // 16384

__device__ float  g_Q[Mc * Dc];
__device__ float  g_K[Mc * Dc];
__device__ __half g_Qh[Mc * Dc];        // h(Q) from gemm_qk epilogue
__device__ __half g_Kh[Mc * Dc];
__device__ __half g_Qsh[Mc * Dc];       // fp16 input activations
__device__ __half g_Ksh[Mc * Dc];
__device__ __half g_WQt[Dc * Dc];       // [n][k] transposed fp16 weights
__device__ __half g_WKt[Dc * Dc];
__device__ __half g_WPt[Dc * Dc];
__device__ float  g_logA[Bc * Hc * Sc];
__device__ float  g_logB[Bc * Hc * Sc];
__device__ float  g_qg[Bc * Hc * DHc];
__device__ float  g_kg[Bc * Dc];

// ===========================================================================
__device__ __forceinline__ uint32_t cvta_smem(const void* p) {
    uint32_t a;
    asm("{ .reg .u64 t; cvta.to.shared.u64 t, %1; cvt.u32.u64 %0, t; }" : "=r"(a) : "l"(p));
    return a;
}
__device__ __forceinline__ void cp16(uint32_t s, const void* g) {
    asm volatile("cp.async.cg.shared.global [%0], [%1], 16;" :: "r"(s), "l"(g));
}
__device__ __forceinline__ void cp_commit() {
    asm volatile("cp.async.commit_group;" ::: "memory");
}
template <int N>
__device__ __forceinline__ void cp_wait() {
    asm volatile("cp.async.wait_group %0;" :: "n"(N) : "memory");
}
__device__ __forceinline__ void ldmx4(uint32_t& r0, uint32_t& r1, uint32_t& r2, uint32_t& r3,
                                      uint32_t addr) {
    asm volatile("ldmatrix.sync.aligned.m8n8.x4.shared.b16 {%0,%1,%2,%3}, [%4];"
                 : "=r"(r0), "=r"(r1), "=r"(r2), "=r"(r3) : "r"(addr));
}
__device__ __forceinline__ void mma_f16(float& c0, float& c1, float& c2, float& c3,
                                        uint32_t a0, uint32_t a1, uint32_t a2, uint32_t a3,
                                        uint32_t b0, uint32_t b1) {
    asm volatile(
        "mma.sync.aligned.m16n8k16.row.col.f32.f16.f16.f32 "
        "{%0,%1,%2,%3}, {%4,%5,%6,%7}, {%8,%9}, {%0,%1,%2,%3};"
        : "+f"(c0), "+f"(c1), "+f"(c2), "+f"(c3)
        : "r"(a0), "r"(a1), "r"(a2), "r"(a3), "r"(b0), "r"(b1));
}
__device__ __forceinline__ uint32_t pack_h2(float x, float y) {
    __half2 h = __floats2half2_rn(x, y);
    return *reinterpret_cast<uint32_t*>(&h);
}
__device__ __forceinline__ uint32_t hscale(uint32_t h2, float2 s) {
    __half2 h = *reinterpret_cast<__half2*>(&h2);
    float2 f = __half22float2(h);
    return pack_h2(f.x * s.x, f.y * s.y);
}

// ===========================================================================
// GEMM: C[M,N] = Ah[M,K](fp16) @ Bt[N,K](fp16)^T.  BM=BN=128, BK=32,
// 128 thr (2x2 warps, 64x64 tiles), fp16 m16n8k16, 4-stage cp.async,
// one __syncthreads per chunk, 2 CTAs/SM (round-12 proven config).
// RES: epilogue += resid.  WH: also store h(C) to Ch.
// SCALEA: scale A fragments by Kg[b, k] (fp32 math, repacked to fp16).
// ===========================================================================
#define RSTRIDE 80
#define TILEB (128 * RSTRIDE)       // 10240
#define STGB (2 * TILEB)            // 20480
#define NSTG 4
#define GSMEM (NSTG * STGB)         // 81920
#define NCH (Dc / 32)               // 32

template <int RES, int WH, int SCALEA>
__device__ __forceinline__ void gemm_body(
    const __half* __restrict__ A, const __half* __restrict__ Bt,
    float* __restrict__ C, __half* __restrict__ Ch,
    const float* __restrict__ resid, const float* __restrict__ Kg)
{
    extern __shared__ char smem[];
    const uint32_t sb = cvta_smem(smem);
    const int tid  = threadIdx.x;
    const int wid  = tid >> 5, lane = tid & 31;
    const int g    = lane >> 2, t = lane & 3;
    const int wm   = wid >> 1, wn = wid & 1;
    const int crow = blockIdx.y * 128, ccol = blockIdx.x * 128;

    const float* kgp = SCALEA ? (Kg + (size_t)(crow / Sc) * Dc) : nullptr;

    // loaders: 4 thr/row (16B fp16 each), 32 rows/pass, 4 passes
    const int lrow = tid >> 2, lseg = tid & 3;
    const __half* Ag = A  + (size_t)(crow + lrow) * Dc + lseg * 8;
    const __half* Bg = Bt + (size_t)(ccol + lrow) * Dc + lseg * 8;
    const uint32_t sA = (uint32_t)(lrow * RSTRIDE + lseg * 16);
    const uint32_t sB = (uint32_t)(TILEB + lrow * RSTRIDE + lseg * 16);

    // ldmatrix per-lane offsets
    const int ltile = lane >> 3, lr = lane & 7;
    uint32_t offA[4], offB[4];
#pragma unroll
    for (int im = 0; im < 4; im++)
        offA[im] = (uint32_t)((wm * 64 + im * 16 + (ltile & 1) * 8 + lr) * RSTRIDE
                              + (ltile >> 1) * 16);
#pragma unroll
    for (int j = 0; j < 4; j++)
        offB[j] = (uint32_t)(TILEB + (wn * 64 + j * 16 + (ltile >> 1) * 8 + lr) * RSTRIDE
                             + (ltile & 1) * 16);

    float acc[4][8][4];
#pragma unroll
    for (int i = 0; i < 4; i++)
#pragma unroll
        for (int j = 0; j < 8; j++)
#pragma unroll
            for (int k = 0; k < 4; k++) acc[i][j][k] = 0.f;

    auto issue = [&](int c) {
        uint32_t base = sb + (uint32_t)(c & (NSTG - 1)) * STGB;
        const __half* ag = Ag + c * 32;
        const __half* bg = Bg + c * 32;
#pragma unroll
        for (int p = 0; p < 4; p++) {
            cp16(base + sA + p * 32 * RSTRIDE, ag + (size_t)p * 32 * Dc);
            cp16(base + sB + p * 32 * RSTRIDE, bg + (size_t)p * 32 * Dc);
        }
        cp_commit();
    };

    issue(0); issue(1); issue(2);

    for (int c = 0; c < NCH; c++) {
        if (c + 2 < NCH)      cp_wait<2>();
        else if (c + 1 < NCH) cp_wait<1>();
        else                  cp_wait<0>();
        __syncthreads();                 // stage c visible; slot (c-1)%4 drained
        if (c + 3 < NCH) issue(c + 3);

        const uint32_t base = sb + (uint32_t)(c & (NSTG - 1)) * STGB;

#pragma unroll
        for (int kk = 0; kk < 2; kk++) {
            uint32_t a[4][4], b[8][2];
#pragma unroll
            for (int im = 0; im < 4; im++)
                ldmx4(a[im][0], a[im][1], a[im][2], a[im][3],
                      base + offA[im] + kk * 32);
#pragma unroll
            for (int j = 0; j < 4; j++) {
                uint32_t r0, r1, r2, r3;
                ldmx4(r0, r1, r2, r3, base + offB[j] + kk * 32);
                b[2 * j][0] = r0;     b[2 * j][1] = r1;
                b[2 * j + 1][0] = r2; b[2 * j + 1][1] = r3;
            }
            if (SCALEA) {
                const int kb = c * 32 + kk * 16;
                float2 s0 = *(const float2*)(kgp + kb + 2 * t);
                float2 s1 = *(const float2*)(kgp + kb + 8 + 2 * t);
#pragma unroll
                for (int im = 0; im < 4; im++) {
                    a[im][0] = hscale(a[im][0], s0);
                    a[im][1] = hscale(a[im][1], s0);
                    a[im][2] = hscale(a[im][2], s1);
                    a[im][3] = hscale(a[im][3], s1);
                }
            }
#pragma unroll
            for (int im = 0; im < 4; im++)
#pragma unroll
                for (int in = 0; in < 8; in++)
                    mma_f16(acc[im][in][0], acc[im][in][1], acc[im][in][2], acc[im][in][3],
                            a[im][0], a[im][1], a[im][2], a[im][3],
                            b[in][0], b[in][1]);
        }
    }
    __syncthreads();

    // epilogue (fragment rows g, g+8; cols 2t, 2t+1)
#pragma unroll
    for (int im = 0; im < 4; im++) {
#pragma unroll
        for (int in = 0; in < 8; in++) {
            const int r0 = crow + wm * 64 + im * 16 + g;
            const int cc = ccol + wn * 64 + in * 8 + 2 * t;
            float2 v0 = make_float2(acc[im][in][0], acc[im][in][1]);
            float2 v1 = make_float2(acc[im][in][2], acc[im][in][3]);
            if (RES) {
                float2 q0 = *(const float2*)(resid + (size_t)r0 * Dc + cc);
                float2 q1 = *(const float2*)(resid + (size_t)(r0 + 8) * Dc + cc);
                v0.x += q0.x; v0.y += q0.y; v1.x += q1.x; v1.y += q1.y;
            }
            *(float2*)(C + (size_t)r0 * Dc + cc) = v0;
            *(float2*)(C + (size_t)(r0 + 8) * Dc + cc) = v1;
            if (WH) {
                *(uint32_t*)(Ch + (size_t)r0 * Dc + cc) = pack_h2(v0.x, v0.y);
                *(uint32_t*)(Ch + (size_t)(r0 + 8) * Dc + cc) = pack_h2(v1.x, v1.y);
            }
        }
    }
}

// fused Q&K projection: blockIdx.z picks the problem; z==0 also emits h(Q)
__global__ __launch_bounds__(128, 2)
void gemm_qk(const __half* __restrict__ Aq, const __half* __restrict__ Ak,
             const __half* __restrict__ Bq, const __half* __restrict__ Bk,
             float* __restrict__ Cq, float* __restrict__ Ck,
             __half* __restrict__ Qh)
{
    if (blockIdx.z == 0) gemm_body<0, 1, 0>(Aq, Bq, Cq, Qh, nullptr, nullptr);
    else                 gemm_body<0, 0, 0>(Ak, Bk, Ck, nullptr, nullptr, nullptr);
}

__global__ __launch_bounds__(128, 2)
void gemm_out(const __half* __restrict__ A, const __half* __restrict__ Bt,
              float* __restrict__ C, const float* __restrict__ resid,
              const float* __restrict__ Kg)
{
    gemm_body<1, 0, 1>(A, Bt, C, nullptr, resid, Kg);
}

// ===========================================================================
// weight transpose + fp16 (3 weights in one launch via z)
// ===========================================================================
__global__ void tcvt_k(const float* __restrict__ W0, const float* __restrict__ W1,
                       const float* __restrict__ W2,
                       __half* __restrict__ T0, __half* __restrict__ T1,
                       __half* __restrict__ T2)
{
    const float* W = (blockIdx.z == 0) ? W0 : (blockIdx.z == 1) ? W1 : W2;
    __half* Wt     = (blockIdx.z == 0) ? T0 : (blockIdx.z == 1) ? T1 : T2;
    __shared__ float tbuf[32][33];
    int n0 = blockIdx.x * 32, k0 = blockIdx.y * 32;
    int tx = threadIdx.x, ty = threadIdx.y;
#pragma unroll
    for (int i = 0; i < 32; i += 8) tbuf[ty + i][tx] = W[(size_t)(k0 + ty + i) * Dc + n0 + tx];
    __syncthreads();
#pragma unroll
    for (int i = 0; i < 32; i += 8)
        Wt[(size_t)(n0 + ty + i) * Dc + k0 + tx] = __float2half_rn(tbuf[tx][ty + i]);
}

// fp32 -> fp16 elementwise, two tensors in one launch (blockIdx.y)
__global__ void cvth2_k(const float* __restrict__ in0, __half* __restrict__ out0,
                        const float* __restrict__ in1, __half* __restrict__ out1, int n4)
{
    int i = blockIdx.x * blockDim.x + threadIdx.x;
    if (i >= n4) return;
    const float* in = blockIdx.y ? in1 : in0;
    __half* out     = blockIdx.y ? out1 : out0;
    float4 v = ((const float4*)in)[i];
    uint2 o = make_uint2(pack_h2(v.x, v.y), pack_h2(v.z, v.w));
    ((uint2*)out)[i] = o;
}

// ===========================================================================
// logitsA: one warp per 4 rows
// ===========================================================================
__global__ void logitsA_k(const float* __restrict__ Wa)
{
    int gw = (blockIdx.x * blockDim.x + threadIdx.x) >> 5;
    int lane = threadIdx.x & 31;
    int b = gw >> 9;
    int s0 = (gw << 2) & 2047;
    const float* q = g_Q + ((size_t)gw << 2) * Dc;

    float acc[4][16];
#pragma unroll
    for (int r = 0; r < 4; r++)
#pragma unroll
        for (int e = 0; e < 16; e++) acc[r][e] = 0.f;

    for (int i = 0; i < 8; i++) {
        int d4 = lane + 32 * i;
        float4 qv[4];
#pragma unroll
        for (int r = 0; r < 4; r++)
            qv[r] = reinterpret_cast<const float4*>(q + (size_t)r * Dc)[d4];
        const float4* wa = reinterpret_cast<const float4*>(Wa) + (size_t)d4 * 16;
#pragma unroll
        for (int dd = 0; dd < 4; dd++) {
            float4 w0 = wa[dd * 4 + 0], w1 = wa[dd * 4 + 1];
            float4 w2 = wa[dd * 4 + 2], w3 = wa[dd * 4 + 3];
            float qs[4];
            qs[0] = (dd == 0) ? qv[0].x : (dd == 1) ? qv[0].y : (dd == 2) ? qv[0].z : qv[0].w;
            qs[1] = (dd == 0) ? qv[1].x : (dd == 1) ? qv[1].y : (dd == 2) ? qv[1].z : qv[1].w;
            qs[2] = (dd == 0) ? qv[2].x : (dd == 1) ? qv[2].y : (dd == 2) ? qv[2].z : qv[2].w;
            qs[3] = (dd == 0) ? qv[3].x : (dd == 1) ? qv[3].y : (dd == 2) ? qv[3].z : qv[3].w;
#pragma unroll
            for (int r = 0; r < 4; r++) {
                acc[r][0]  += qs[r] * w0.x; acc[r][1]  += qs[r] * w0.y;
                acc[r][2]  += qs[r] * w0.z; acc[r][3]  += qs[r] * w0.w;
                acc[r][4]  += qs[r] * w1.x; acc[r][5]  += qs[r] * w1.y;
                acc[r][6]  += qs[r] * w1.z; acc[r][7]  += qs[r] * w1.w;
                acc[r][8]  += qs[r] * w2.x; acc[r][9]  += qs[r] * w2.y;
                acc[r][10] += qs[r] * w2.z; acc[r][11] += qs[r] * w2.w;
                acc[r][12] += qs[r] * w3.x; acc[r][13] += qs[r] * w3.y;
                acc[r][14] += qs[r] * w3.z; acc[r][15] += qs[r] * w3.w;
            }
        }
    }

#pragma unroll
    for (int e = 0; e < 16; e++) {
        float v0 = acc[0][e], v1 = acc[1][e], v2 = acc[2][e], v3 = acc[3][e];
#pragma unroll
        for (int o = 16; o; o >>= 1) {
            v0 += __shfl_xor_sync(0xffffffffu, v0, o);
            v1 += __shfl_xor_sync(0xffffffffu, v1, o);
            v2 += __shfl_xor_sync(0xffffffffu, v2, o);
            v3 += __shfl_xor_sync(0xffffffffu, v3, o);
        }
        if (lane == e) {
            float* dst = g_logA + (b * Hc + e) * Sc + s0;
            dst[0] = v0 * 0.125f; dst[1] = v1 * 0.125f;
            dst[2] = v2 * 0.125f; dst[3] = v3 * 0.125f;
        }
    }
}

// ===========================================================================
// logitsB: one warp per 4 scrambled rows
// ===========================================================================
__global__ void logitsB_k(const float* __restrict__ Wb)
{
    int gw = (blockIdx.x * blockDim.x + threadIdx.x) >> 5;
    int lane = threadIdx.x & 31;
    int b = gw >> 9;
    int spL = (gw << 2) & 2047;
    int h0 = spL >> 7;
    int s0 = (spL & 127) << 4;

    const float* qgv = g_qg + (b * Hc + h0) * DHc;
    const float* Kb  = g_K + ((size_t)(b * Sc + s0)) * Dc + h0 * DHc;

    float acc[4][16];
#pragma unroll
    for (int r = 0; r < 4; r++)
#pragma unroll
        for (int e = 0; e < 16; e++) acc[r][e] = 0.f;

    for (int i = 0; i < 32; i++) {
        int k = lane + 32 * i;
        int tt = k >> 6, j = k & 63;
        float qv = qgv[j];
        float vr[4];
#pragma unroll
        for (int r = 0; r < 4; r++)
            vr[r] = Kb[(size_t)(r * 16 + tt) * Dc + j] * qv;
        const float4* w4 = reinterpret_cast<const float4*>(Wb + k * 16);
        float4 w0 = w4[0], w1 = w4[1], w2 = w4[2], w3 = w4[3];
#pragma unroll
        for (int r = 0; r < 4; r++) {
            acc[r][0]  += vr[r] * w0.x; acc[r][1]  += vr[r] * w0.y;
            acc[r][2]  += vr[r] * w0.z; acc[r][3]  += vr[r] * w0.w;
            acc[r][4]  += vr[r] * w1.x; acc[r][5]  += vr[r] * w1.y;
            acc[r][6]  += vr[r] * w1.z; acc[r][7]  += vr[r] * w1.w;
            acc[r][8]  += vr[r] * w2.x; acc[r][9]  += vr[r] * w2.y;
            acc[r][10] += vr[r] * w2.z; acc[r][11] += vr[r] * w2.w;
            acc[r][12] += vr[r] * w3.x; acc[r][13] += vr[r] * w3.y;
            acc[r][14] += vr[r] * w3.z; acc[r][15] += vr[r] * w3.w;
        }
    }

#pragma unroll
    for (int e = 0; e < 16; e++) {
        float v0 = acc[0][e], v1 = acc[1][e], v2 = acc[2][e], v3 = acc[3][e];
#pragma unroll
        for (int o = 16; o; o >>= 1) {
            v0 += __shfl_xor_sync(0xffffffffu, v0, o);
            v1 += __shfl_xor_sync(0xffffffffu, v1, o);
            v2 += __shfl_xor_sync(0xffffffffu, v2, o);
            v3 += __shfl_xor_sync(0xffffffffu, v3, o);
        }
        if (lane == e) {
            float* dst = g_logB + (b * Hc + e) * Sc + spL;
            dst[0] = v0 * 0.125f; dst[1] = v1 * 0.125f;
            dst[2] = v2 * 0.125f; dst[3] = v3 * 0.125f;
        }
    }
}

// ===========================================================================
__global__ void pool_k(const float* __restrict__ logits, const float* __restrict__ X,
                       const float* __restrict__ qscale, float* __restrict__ out)
{
    int bh = blockIdx.x;
    int b = bh >> 4, h = bh & 15;
    const float* lg = logits + bh * Sc;

    __shared__ float sE[Sc];
    __shared__ float red[16];
    __shared__ float part[8][DHc];

    int tid = threadIdx.x, lane = tid & 31, warp = tid >> 5;

    float mx = -1e30f;
    for (int s = tid; s < Sc; s += 512) mx = fmaxf(mx, lg[s]);
#pragma unroll
    for (int o = 16; o; o >>= 1) mx = fmaxf(mx, __shfl_xor_sync(0xffffffffu, mx, o));
    if (lane == 0) red[warp] = mx;
    __syncthreads();
    mx = red[0];
#pragma unroll
    for (int i = 1; i < 16; i++) mx = fmaxf(mx, red[i]);
    __syncthreads();

    float sum = 0.f;
    for (int s = tid; s < Sc; s += 512) {
        float e = __expf(lg[s] - mx);
        sE[s] = e;
        sum += e;
    }
#pragma unroll
    for (int o = 16; o; o >>= 1) sum += __shfl_xor_sync(0xffffffffu, sum, o);
    if (lane == 0) red[warp] = sum;
    __syncthreads();
    float tot = 0.f;
#pragma unroll
    for (int i = 0; i < 16; i++) tot += red[i];
    float inv = 1.0f / tot;

    int j = tid & 63, gg = tid >> 6;
    const float* Xb = X + ((size_t)b * Sc) * Dc + h * DHc + j;
    float a0 = 0.f, a1 = 0.f, a2 = 0.f, a3 = 0.f;
    for (int s = gg; s < Sc; s += 32) {
        a0 += sE[s]      * Xb[(size_t)s * Dc];
        a1 += sE[s + 8]  * Xb[(size_t)(s + 8)  * Dc];
        a2 += sE[s + 16] * Xb[(size_t)(s + 16) * Dc];
        a3 += sE[s + 24] * Xb[(size_t)(s + 24) * Dc];
    }
    part[gg][j] = (a0 + a1) + (a2 + a3);
    __syncthreads();
    if (gg == 0) {
        float v = 0.f;
#pragma unroll
        for (int i = 0; i < 8; i++) v += part[i][j];
        v *= inv;
        if (qscale) v *= qscale[bh * DHc + j];
        out[bh * DHc + j] = v;
    }
}

// ===========================================================================
extern "C" void kernel_launch(void* const* d_in, const int* in_sizes, int n_in,
                              void* d_out, int out_size)
{
    const float* Qseq = (const float*)d_in[0];
    const float* Kseq = (const float*)d_in[1];
    const float* WQ = (const float*)d_in[3];
    const float* WK = (const float*)d_in[4];
    const float* Wa = (const float*)d_in[5];
    const float* Wb = (const float*)d_in[6];
    const float* WP = (const float*)d_in[7];
    float* out = (float*)d_out;

    float *pQ, *pK, *pLA, *pLB, *pqg, *pkg;
    __half *pQh, *pQsh, *pKsh, *pWQ, *pWK, *pWP;
    cudaGetSymbolAddress((void**)&pQ,   g_Q);
    cudaGetSymbolAddress((void**)&pK,   g_K);
    cudaGetSymbolAddress((void**)&pQh,  g_Qh);
    cudaGetSymbolAddress((void**)&pQsh, g_Qsh);
    cudaGetSymbolAddress((void**)&pKsh, g_Ksh);
    cudaGetSymbolAddress((void**)&pWQ,  g_WQt);
    cudaGetSymbolAddress((void**)&pWK,  g_WKt);
    cudaGetSymbolAddress((void**)&pWP,  g_WPt);
    cudaGetSymbolAddress((void**)&pLA,  g_logA);
    cudaGetSymbolAddress((void**)&pLB,  g_logB);
    cudaGetSymbolAddress((void**)&pqg,  g_qg);
    cudaGetSymbolAddress((void**)&pkg,  g_kg);

    cudaFuncSetAttribute(gemm_qk,  cudaFuncAttributeMaxDynamicSharedMemorySize, GSMEM);
    cudaFuncSetAttribute(gemm_out, cudaFuncAttributeMaxDynamicSharedMemorySize, GSMEM);

    const int big4 = Mc * Dc / 4;
    dim3 tg(32, 32, 3), tb(32, 8);
    dim3 cg((big4 + 255) / 256, 2);
    dim3 ggqk(Dc / 128, Mc / 128, 2);
    dim3 gg(Dc / 128, Mc / 128);

    tcvt_k<<<tg, tb>>>(WQ, WK, WP, pWQ, pWK, pWP);                       // 1
    cvth2_k<<<cg, 256>>>(Qseq, pQsh, Kseq, pKsh, big4);                  // 2
    gemm_qk<<<ggqk, 128, GSMEM>>>(pQsh, pKsh, pWQ, pWK, pQ, pK, pQh);    // 3
    logitsA_k<<<Mc / 4 / 8, 256>>>(Wa);                                  // 4 <- profiled
    pool_k<<<Bc * Hc, 512>>>(pLA, pQ, nullptr, pqg);                     // 5
    logitsB_k<<<Mc / 4 / 8, 256>>>(Wb);                                  // 6
    pool_k<<<Bc * Hc, 512>>>(pLB, pK, pqg, pkg);                         // 7
    gemm_out<<<gg, 128, GSMEM>>>(pQh, pWP, out, pQ, pkg);                // 8
}

// round 15
// speedup vs baseline: 1.0898x; 1.0898x over previous
#include <cuda_runtime.h>
#include <cuda_fp16.h>
#include <cstdint>

// ---------------------------------------------------------------------------
// Fastformer — fp16 SS mma.sync GEMMs (round-12 core, 4-stage, 2 CTA/SM),
// gemm_qk emits h(Q)/h(K); logits kernels: 8 rows/warp on fp16 operands.
// ---------------------------------------------------------------------------

#define Bc 8
#define Sc 2048
#define Dc 1024
#define Hc 16
#define DHc 64
#define Mc (Bc * Sc)   // 16384

__device__ float  g_Q[Mc * Dc];
__device__ float  g_K[Mc * Dc];
__device__ __half g_Qh[Mc * Dc];        // h(Q) from gemm_qk epilogue
__device__ __half g_Kh[Mc * Dc];        // h(K) from gemm_qk epilogue
__device__ __half g_Qsh[Mc * Dc];       // fp16 inputs; reused by scaleh
__device__ __half g_Ksh[Mc * Dc];
__device__ __half g_WQt[Dc * Dc];       // [n][k] transposed fp16 weights
__device__ __half g_WKt[Dc * Dc];
__device__ __half g_WPt[Dc * Dc];
__device__ __half g_Wah[Dc * Hc];       // fp16 Wa (row-major [d][e])
__device__ __half g_Wbh[Dc * Hc];
__device__ float  g_logA[Bc * Hc * Sc];
__device__ float  g_logB[Bc * Hc * Sc];
__device__ float  g_qg[Bc * Hc * DHc];
__device__ float  g_kg[Bc * Dc];

// ===========================================================================
__device__ __forceinline__ uint32_t cvta_smem(const void* p) {
    uint32_t a;
    asm("{ .reg .u64 t; cvta.to.shared.u64 t, %1; cvt.u32.u64 %0, t; }" : "=r"(a) : "l"(p));
    return a;
}
__device__ __forceinline__ void cp16(uint32_t s, const void* g) {
    asm volatile("cp.async.cg.shared.global [%0], [%1], 16;" :: "r"(s), "l"(g));
}
__device__ __forceinline__ void cp_commit() {
    asm volatile("cp.async.commit_group;" ::: "memory");
}
template <int N>
__device__ __forceinline__ void cp_wait() {
    asm volatile("cp.async.wait_group %0;" :: "n"(N) : "memory");
}
__device__ __forceinline__ void ldmx4(uint32_t& r0, uint32_t& r1, uint32_t& r2, uint32_t& r3,
                                      uint32_t addr) {
    asm volatile("ldmatrix.sync.aligned.m8n8.x4.shared.b16 {%0,%1,%2,%3}, [%4];"
                 : "=r"(r0), "=r"(r1), "=r"(r2), "=r"(r3) : "r"(addr));
}
__device__ __forceinline__ void mma_f16(float& c0, float& c1, float& c2, float& c3,
                                        uint32_t a0, uint32_t a1, uint32_t a2, uint32_t a3,
                                        uint32_t b0, uint32_t b1) {
    asm volatile(
        "mma.sync.aligned.m16n8k16.row.col.f32.f16.f16.f32 "
        "{%0,%1,%2,%3}, {%4,%5,%6,%7}, {%8,%9}, {%0,%1,%2,%3};"
        : "+f"(c0), "+f"(c1), "+f"(c2), "+f"(c3)
        : "r"(a0), "r"(a1), "r"(a2), "r"(a3), "r"(b0), "r"(b1));
}
__device__ __forceinline__ uint32_t pack_h2(float x, float y) {
    __half2 h = __floats2half2_rn(x, y);
    return *reinterpret_cast<uint32_t*>(&h);
}

// ===========================================================================
// GEMM (round-12 core): BM=BN=128, BK=32, 128 thr, 4-stage, 1 barrier/chunk.
// RES: epilogue += resid.  WH: also store h(C) to Ch.
// ===========================================================================
#define RSTRIDE 80
#define TILEB (128 * RSTRIDE)       // 10240
#define STGB (2 * TILEB)            // 20480
#define NSTG 4
#define GSMEM (NSTG * STGB)         // 81920
#define NCH (Dc / 32)               // 32

template <int RES, int WH>
__device__ __forceinline__ void gemm_body(
    const __half* __restrict__ A, const __half* __restrict__ Bt,
    float* __restrict__ C, __half* __restrict__ Ch,
    const float* __restrict__ resid)
{
    extern __shared__ char smem[];
    const uint32_t sb = cvta_smem(smem);
    const int tid  = threadIdx.x;
    const int wid  = tid >> 5, lane = tid & 31;
    const int g    = lane >> 2, t = lane & 3;
    const int wm   = wid >> 1, wn = wid & 1;
    const int crow = blockIdx.y * 128, ccol = blockIdx.x * 128;

    const int lrow = tid >> 2, lseg = tid & 3;
    const __half* Ag = A  + (size_t)(crow + lrow) * Dc + lseg * 8;
    const __half* Bg = Bt + (size_t)(ccol + lrow) * Dc + lseg * 8;
    const uint32_t sA = (uint32_t)(lrow * RSTRIDE + lseg * 16);
    const uint32_t sB = (uint32_t)(TILEB + lrow * RSTRIDE + lseg * 16);

    const int ltile = lane >> 3, lr = lane & 7;
    uint32_t offA[4], offB[4];
#pragma unroll
    for (int im = 0; im < 4; im++)
        offA[im] = (uint32_t)((wm * 64 + im * 16 + (ltile & 1) * 8 + lr) * RSTRIDE
                              + (ltile >> 1) * 16);
#pragma unroll
    for (int j = 0; j < 4; j++)
        offB[j] = (uint32_t)(TILEB + (wn * 64 + j * 16 + (ltile >> 1) * 8 + lr) * RSTRIDE
                             + (ltile & 1) * 16);

    float acc[4][8][4];
#pragma unroll
    for (int i = 0; i < 4; i++)
#pragma unroll
        for (int j = 0; j < 8; j++)
#pragma unroll
            for (int k = 0; k < 4; k++) acc[i][j][k] = 0.f;

    auto issue = [&](int c) {
        uint32_t base = sb + (uint32_t)(c & (NSTG - 1)) * STGB;
        const __half* ag = Ag + c * 32;
        const __half* bg = Bg + c * 32;
#pragma unroll
        for (int p = 0; p < 4; p++) {
            cp16(base + sA + p * 32 * RSTRIDE, ag + (size_t)p * 32 * Dc);
            cp16(base + sB + p * 32 * RSTRIDE, bg + (size_t)p * 32 * Dc);
        }
        cp_commit();
    };

    issue(0); issue(1); issue(2);

    for (int c = 0; c < NCH; c++) {
        if (c + 2 < NCH)      cp_wait<2>();
        else if (c + 1 < NCH) cp_wait<1>();
        else                  cp_wait<0>();
        __syncthreads();
        if (c + 3 < NCH) issue(c + 3);

        const uint32_t base = sb + (uint32_t)(c & (NSTG - 1)) * STGB;

#pragma unroll
        for (int kk = 0; kk < 2; kk++) {
            uint32_t a[4][4], b[8][2];
#pragma unroll
            for (int im = 0; im < 4; im++)
                ldmx4(a[im][0], a[im][1], a[im][2], a[im][3],
                      base + offA[im] + kk * 32);
#pragma unroll
            for (int j = 0; j < 4; j++) {
                uint32_t r0, r1, r2, r3;
                ldmx4(r0, r1, r2, r3, base + offB[j] + kk * 32);
                b[2 * j][0] = r0;     b[2 * j][1] = r1;
                b[2 * j + 1][0] = r2; b[2 * j + 1][1] = r3;
            }
#pragma unroll
            for (int im = 0; im < 4; im++)
#pragma unroll
                for (int in = 0; in < 8; in++)
                    mma_f16(acc[im][in][0], acc[im][in][1], acc[im][in][2], acc[im][in][3],
                            a[im][0], a[im][1], a[im][2], a[im][3],
                            b[in][0], b[in][1]);
        }
    }
    __syncthreads();

#pragma unroll
    for (int im = 0; im < 4; im++) {
#pragma unroll
        for (int in = 0; in < 8; in++) {
            const int r0 = crow + wm * 64 + im * 16 + g;
            const int cc = ccol + wn * 64 + in * 8 + 2 * t;
            float2 v0 = make_float2(acc[im][in][0], acc[im][in][1]);
            float2 v1 = make_float2(acc[im][in][2], acc[im][in][3]);
            if (RES) {
                float2 q0 = *(const float2*)(resid + (size_t)r0 * Dc + cc);
                float2 q1 = *(const float2*)(resid + (size_t)(r0 + 8) * Dc + cc);
                v0.x += q0.x; v0.y += q0.y; v1.x += q1.x; v1.y += q1.y;
            }
            *(float2*)(C + (size_t)r0 * Dc + cc) = v0;
            *(float2*)(C + (size_t)(r0 + 8) * Dc + cc) = v1;
            if (WH) {
                *(uint32_t*)(Ch + (size_t)r0 * Dc + cc) = pack_h2(v0.x, v0.y);
                *(uint32_t*)(Ch + (size_t)(r0 + 8) * Dc + cc) = pack_h2(v1.x, v1.y);
            }
        }
    }
}

__global__ __launch_bounds__(128, 2)
void gemm_qk(const __half* __restrict__ Aq, const __half* __restrict__ Ak,
             const __half* __restrict__ Bq, const __half* __restrict__ Bk,
             float* __restrict__ Cq, float* __restrict__ Ck,
             __half* __restrict__ Qh, __half* __restrict__ Kh)
{
    if (blockIdx.z == 0) gemm_body<0, 1>(Aq, Bq, Cq, Qh, nullptr);
    else                 gemm_body<0, 1>(Ak, Bk, Ck, Kh, nullptr);
}

__global__ __launch_bounds__(128, 2)
void gemm_out(const __half* __restrict__ A, const __half* __restrict__ Bt,
              float* __restrict__ C, const float* __restrict__ resid)
{
    gemm_body<1, 0>(A, Bt, C, nullptr, resid);
}

// ===========================================================================
// weight prep: z<3 -> transpose+fp16 of 1024x1024 W; z==3 -> fp16 copies of
// Wa (bx==0) / Wb (bx==1), no transpose (row-major [d][e]).
// ===========================================================================
__global__ void tcvt_k(const float* __restrict__ W0, const float* __restrict__ W1,
                       const float* __restrict__ W2,
                       __half* __restrict__ T0, __half* __restrict__ T1,
                       __half* __restrict__ T2,
                       const float* __restrict__ Wa, const float* __restrict__ Wb,
                       __half* __restrict__ Tah, __half* __restrict__ Tbh)
{
    int tx = threadIdx.x, ty = threadIdx.y;
    if (blockIdx.z == 3) {
        if (blockIdx.x > 1) return;
        const float* S = blockIdx.x ? Wb : Wa;
        __half* D      = blockIdx.x ? Tbh : Tah;
        int k0 = blockIdx.y * 32;
        if (tx < 16) {
#pragma unroll
            for (int i = 0; i < 32; i += 8)
                D[(k0 + ty + i) * Hc + tx] = __float2half_rn(S[(k0 + ty + i) * Hc + tx]);
        }
        return;
    }
    const float* W = (blockIdx.z == 0) ? W0 : (blockIdx.z == 1) ? W1 : W2;
    __half* Wt     = (blockIdx.z == 0) ? T0 : (blockIdx.z == 1) ? T1 : T2;
    __shared__ float tbuf[32][33];
    int n0 = blockIdx.x * 32, k0 = blockIdx.y * 32;
#pragma unroll
    for (int i = 0; i < 32; i += 8) tbuf[ty + i][tx] = W[(size_t)(k0 + ty + i) * Dc + n0 + tx];
    __syncthreads();
#pragma unroll
    for (int i = 0; i < 32; i += 8)
        Wt[(size_t)(n0 + ty + i) * Dc + k0 + tx] = __float2half_rn(tbuf[tx][ty + i]);
}

// fp32 -> fp16 elementwise, two tensors in one launch (blockIdx.y)
__global__ void cvth2_k(const float* __restrict__ in0, __half* __restrict__ out0,
                        const float* __restrict__ in1, __half* __restrict__ out1, int n4)
{
    int i = blockIdx.x * blockDim.x + threadIdx.x;
    if (i >= n4) return;
    const float* in = blockIdx.y ? in1 : in0;
    __half* out     = blockIdx.y ? out1 : out0;
    float4 v = ((const float4*)in)[i];
    uint2 o = make_uint2(pack_h2(v.x, v.y), pack_h2(v.z, v.w));
    ((uint2*)out)[i] = o;
}

// g_Qsh[m][k] = half(g_Q[m][k] * kg[b,k])
__global__ void scaleh_k()
{
    int i = blockIdx.x * blockDim.x + threadIdx.x;
    int k4 = i & 255, m = i >> 8, b = m >> 11;
    float4 v = ((const float4*)g_Q)[i];
    float4 s = ((const float4*)g_kg)[b * 256 + k4];
    uint2 o = make_uint2(pack_h2(v.x * s.x, v.y * s.y), pack_h2(v.z * s.z, v.w * s.w));
    ((uint2*)g_Qsh)[i] = o;
}

// ===========================================================================
// logitsA: one warp per 8 rows, fp16 Q + fp16 Wa, fp32 accumulate.
// ===========================================================================
__global__ __launch_bounds__(128)
void logitsA_k()
{
    int gw = (blockIdx.x * blockDim.x + threadIdx.x) >> 5;   // 0..2047
    int lane = threadIdx.x & 31;
    int b = gw >> 8;
    int s0 = (gw & 255) * 8;
    const __half* q = g_Qh + ((size_t)gw * 8) * Dc;

    float acc[8][16];
#pragma unroll
    for (int r = 0; r < 8; r++)
#pragma unroll
        for (int e = 0; e < 16; e++) acc[r][e] = 0.f;

    for (int i = 0; i < 4; i++) {
        int d8 = lane + 32 * i;                  // chunk of 8 d's, d = d8*8
        uint4 qv[8];
#pragma unroll
        for (int r = 0; r < 8; r++)
            qv[r] = *reinterpret_cast<const uint4*>(q + (size_t)r * Dc + d8 * 8);
        const __half* wa = g_Wah + (size_t)d8 * 8 * Hc;
#pragma unroll
        for (int dd = 0; dd < 8; dd++) {
            uint4 w0 = *reinterpret_cast<const uint4*>(wa + dd * Hc);
            uint4 w1 = *reinterpret_cast<const uint4*>(wa + dd * Hc + 8);
            float we[16];
            {
                const __half2* wp0 = reinterpret_cast<const __half2*>(&w0);
                const __half2* wp1 = reinterpret_cast<const __half2*>(&w1);
#pragma unroll
                for (int p = 0; p < 4; p++) {
                    float2 f0 = __half22float2(wp0[p]);
                    float2 f1 = __half22float2(wp1[p]);
                    we[2 * p] = f0.x;     we[2 * p + 1] = f0.y;
                    we[8 + 2 * p] = f1.x; we[8 + 2 * p + 1] = f1.y;
                }
            }
#pragma unroll
            for (int r = 0; r < 8; r++) {
                const __half* qh = reinterpret_cast<const __half*>(&qv[r]);
                float qf = __half2float(qh[dd]);
#pragma unroll
                for (int e = 0; e < 16; e++) acc[r][e] += qf * we[e];
            }
        }
    }

#pragma unroll
    for (int e = 0; e < 16; e++) {
        float v[8];
#pragma unroll
        for (int r = 0; r < 8; r++) v[r] = acc[r][e];
#pragma unroll
        for (int o = 16; o; o >>= 1)
#pragma unroll
            for (int r = 0; r < 8; r++) v[r] += __shfl_xor_sync(0xffffffffu, v[r], o);
        if (lane == e) {
            float* dst = g_logA + (b * Hc + e) * Sc + s0;
#pragma unroll
            for (int r = 0; r < 8; r++) dst[r] = v[r] * 0.125f;
        }
    }
}

// ===========================================================================
// logitsB: one warp per 8 scrambled rows, fp16 K + fp16 Wb.
// ===========================================================================
__global__ __launch_bounds__(128)
void logitsB_k()
{
    int gw = (blockIdx.x * blockDim.x + threadIdx.x) >> 5;   // 0..2047
    int lane = threadIdx.x & 31;
    int b = gw >> 8;
    int spL = (gw & 255) * 8;
    int h0 = spL >> 7;
    int s0 = (spL & 127) << 4;

    const float* qgv = g_qg + (b * Hc + h0) * DHc;
    const __half* Kb = g_Kh + ((size_t)(b * Sc + s0)) * Dc + h0 * DHc;

    float acc[8][16];
#pragma unroll
    for (int r = 0; r < 8; r++)
#pragma unroll
        for (int e = 0; e < 16; e++) acc[r][e] = 0.f;

    for (int i = 0; i < 32; i++) {
        int k = lane + 32 * i;
        int tt = k >> 6, j = k & 63;
        float qv = qgv[j];
        float vr[8];
#pragma unroll
        for (int r = 0; r < 8; r++)
            vr[r] = __half2float(Kb[(size_t)(r * 16 + tt) * Dc + j]) * qv;

        uint4 w0 = *reinterpret_cast<const uint4*>(g_Wbh + (size_t)k * Hc);
        uint4 w1 = *reinterpret_cast<const uint4*>(g_Wbh + (size_t)k * Hc + 8);
        float we[16];
        {
            const __half2* wp0 = reinterpret_cast<const __half2*>(&w0);
            const __half2* wp1 = reinterpret_cast<const __half2*>(&w1);
#pragma unroll
            for (int p = 0; p < 4; p++) {
                float2 f0 = __half22float2(wp0[p]);
                float2 f1 = __half22float2(wp1[p]);
                we[2 * p] = f0.x;     we[2 * p + 1] = f0.y;
                we[8 + 2 * p] = f1.x; we[8 + 2 * p + 1] = f1.y;
            }
        }
#pragma unroll
        for (int r = 0; r < 8; r++)
#pragma unroll
            for (int e = 0; e < 16; e++) acc[r][e] += vr[r] * we[e];
    }

#pragma unroll
    for (int e = 0; e < 16; e++) {
        float v[8];
#pragma unroll
        for (int r = 0; r < 8; r++) v[r] = acc[r][e];
#pragma unroll
        for (int o = 16; o; o >>= 1)
#pragma unroll
            for (int r = 0; r < 8; r++) v[r] += __shfl_xor_sync(0xffffffffu, v[r], o);
        if (lane == e) {
            float* dst = g_logB + (b * Hc + e) * Sc + spL;
#pragma unroll
            for (int r = 0; r < 8; r++) dst[r] = v[r] * 0.125f;
        }
    }
}

// ===========================================================================
__global__ void pool_k(const float* __restrict__ logits, const float* __restrict__ X,
                       const float* __restrict__ qscale, float* __restrict__ out)
{
    int bh = blockIdx.x;
    int b = bh >> 4, h = bh & 15;
    const float* lg = logits + bh * Sc;

    __shared__ float sE[Sc];
    __shared__ float red[16];
    __shared__ float part[8][DHc];

    int tid = threadIdx.x, lane = tid & 31, warp = tid >> 5;

    float mx = -1e30f;
    for (int s = tid; s < Sc; s += 512) mx = fmaxf(mx, lg[s]);
#pragma unroll
    for (int o = 16; o; o >>= 1) mx = fmaxf(mx, __shfl_xor_sync(0xffffffffu, mx, o));
    if (lane == 0) red[warp] = mx;
    __syncthreads();
    mx = red[0];
#pragma unroll
    for (int i = 1; i < 16; i++) mx = fmaxf(mx, red[i]);
    __syncthreads();

    float sum = 0.f;
    for (int s = tid; s < Sc; s += 512) {
        float e = __expf(lg[s] - mx);
        sE[s] = e;
        sum += e;
    }
#pragma unroll
    for (int o = 16; o; o >>= 1) sum += __shfl_xor_sync(0xffffffffu, sum, o);
    if (lane == 0) red[warp] = sum;
    __syncthreads();
    float tot = 0.f;
#pragma unroll
    for (int i = 0; i < 16; i++) tot += red[i];
    float inv = 1.0f / tot;

    int j = tid & 63, gg = tid >> 6;
    const float* Xb = X + ((size_t)b * Sc) * Dc + h * DHc + j;
    float a0 = 0.f, a1 = 0.f, a2 = 0.f, a3 = 0.f;
    for (int s = gg; s < Sc; s += 32) {
        a0 += sE[s]      * Xb[(size_t)s * Dc];
        a1 += sE[s + 8]  * Xb[(size_t)(s + 8)  * Dc];
        a2 += sE[s + 16] * Xb[(size_t)(s + 16) * Dc];
        a3 += sE[s + 24] * Xb[(size_t)(s + 24) * Dc];
    }
    part[gg][j] = (a0 + a1) + (a2 + a3);
    __syncthreads();
    if (gg == 0) {
        float v = 0.f;
#pragma unroll
        for (int i = 0; i < 8; i++) v += part[i][j];
        v *= inv;
        if (qscale) v *= qscale[bh * DHc + j];
        out[bh * DHc + j] = v;
    }
}

// ===========================================================================
extern "C" void kernel_launch(void* const* d_in, const int* in_sizes, int n_in,
                              void* d_out, int out_size)
{
    const float* Qseq = (const float*)d_in[0];
    const float* Kseq = (const float*)d_in[1];
    const float* WQ = (const float*)d_in[3];
    const float* WK = (const float*)d_in[4];
    const float* Wa = (const float*)d_in[5];
    const float* Wb = (const float*)d_in[6];
    const float* WP = (const float*)d_in[7];
    float* out = (float*)d_out;

    float *pQ, *pK, *pLA, *pLB, *pqg, *pkg;
    __half *pQh, *pKh, *pQsh, *pKsh, *pWQ, *pWK, *pWP, *pWah, *pWbh;
    cudaGetSymbolAddress((void**)&pQ,   g_Q);
    cudaGetSymbolAddress((void**)&pK,   g_K);
    cudaGetSymbolAddress((void**)&pQh,  g_Qh);
    cudaGetSymbolAddress((void**)&pKh,  g_Kh);
    cudaGetSymbolAddress((void**)&pQsh, g_Qsh);
    cudaGetSymbolAddress((void**)&pKsh, g_Ksh);
    cudaGetSymbolAddress((void**)&pWQ,  g_WQt);
    cudaGetSymbolAddress((void**)&pWK,  g_WKt);
    cudaGetSymbolAddress((void**)&pWP,  g_WPt);
    cudaGetSymbolAddress((void**)&pWah, g_Wah);
    cudaGetSymbolAddress((void**)&pWbh, g_Wbh);
    cudaGetSymbolAddress((void**)&pLA,  g_logA);
    cudaGetSymbolAddress((void**)&pLB,  g_logB);
    cudaGetSymbolAddress((void**)&pqg,  g_qg);
    cudaGetSymbolAddress((void**)&pkg,  g_kg);

    cudaFuncSetAttribute(gemm_qk,  cudaFuncAttributeMaxDynamicSharedMemorySize, GSMEM);
    cudaFuncSetAttribute(gemm_out, cudaFuncAttributeMaxDynamicSharedMemorySize, GSMEM);

    const int big4 = Mc * Dc / 4;
    dim3 tg(32, 32, 4), tb(32, 8);
    dim3 cg((big4 + 255) / 256, 2);
    dim3 ggqk(Dc / 128, Mc / 128, 2);
    dim3 gg(Dc / 128, Mc / 128);

    tcvt_k<<<tg, tb>>>(WQ, WK, WP, pWQ, pWK, pWP, Wa, Wb, pWah, pWbh);     // 1
    cvth2_k<<<cg, 256>>>(Qseq, pQsh, Kseq, pKsh, big4);                    // 2
    gemm_qk<<<ggqk, 128, GSMEM>>>(pQsh, pKsh, pWQ, pWK, pQ, pK, pQh, pKh); // 3
    logitsA_k<<<Mc / 8 / 4, 128>>>();                                      // 4 <- profiled
    pool_k<<<Bc * Hc, 512>>>(pLA, pQ, nullptr, pqg);                       // 5
    logitsB_k<<<Mc / 8 / 4, 128>>>();                                      // 6
    pool_k<<<Bc * Hc, 512>>>(pLB, pK, pqg, pkg);                           // 7
    scaleh_k<<<big4 / 256, 256>>>();                                       // 8
    gemm_out<<<gg, 128, GSMEM>>>(pQsh, pWP, out, pQ);                      // 9
}